// round 9
// baseline (speedup 1.0000x reference)
#include <cuda_runtime.h>
#include <cstdint>

// Problem constants
#define MM 8192
#define NN 8192
#define KK 4096
#define TMT 128
#define TNT 128
#define STAGES 4
#define K_ITERS 32            // 32 groups of K=128 (= GROUPSIZE)

// Static scratch (allocation-free rule: __device__ globals): 3 x 32 MB + 32 KB
__device__ int8_t g_Ahi[(size_t)MM * KK];
__device__ int8_t g_Alo[(size_t)MM * KK];
__device__ int8_t g_W  [(size_t)NN * KK];
__device__ float  g_alpha[MM];

// ---------------------------------------------------------------------------
// Prep A: per-row 15-bit quantization. a_int = round(A * 16256/rowmax),
// a_hi = (a_int+64)>>7 in [-127,127], a_lo = a_int - (a_hi<<7) in [-64,63].
// One block per row; thread t handles 16 contiguous elems.
// ---------------------------------------------------------------------------
__global__ void prep_a_kernel(const float* __restrict__ A, int8_t* __restrict__ Ahi,
                              int8_t* __restrict__ Alo, float* __restrict__ alpha) {
    __shared__ float red[8];
    int m = blockIdx.x, tid = threadIdx.x, lid = tid & 31, wid = tid >> 5;
    const float* row = A + (size_t)m * KK;
    float x[16];
    float4* xv = reinterpret_cast<float4*>(x);
#pragma unroll
    for (int i = 0; i < 4; i++)
        xv[i] = reinterpret_cast<const float4*>(row + tid * 16)[i];
    float mx = 0.f;
#pragma unroll
    for (int i = 0; i < 16; i++) mx = fmaxf(mx, fabsf(x[i]));
#pragma unroll
    for (int o = 16; o; o >>= 1) mx = fmaxf(mx, __shfl_xor_sync(0xFFFFFFFFu, mx, o));
    if (lid == 0) red[wid] = mx;
    __syncthreads();
    mx = red[0];
#pragma unroll
    for (int i = 1; i < 8; i++) mx = fmaxf(mx, red[i]);
    if (mx < 1e-20f) mx = 1e-20f;
    float inv = 16256.0f / mx;
    if (tid == 0) alpha[m] = mx * (1.0f / 16256.0f);
    uint32_t hw[4], lw[4];
#pragma unroll
    for (int w = 0; w < 4; w++) {
        uint32_t hu = 0, lu = 0;
#pragma unroll
        for (int j = 0; j < 4; j++) {
            int ai = __float2int_rn(x[w * 4 + j] * inv);
            int hi = (ai + 64) >> 7;
            int lo = ai - (hi << 7);
            hu |= (uint32_t)(hi & 255) << (8 * j);
            lu |= (uint32_t)(lo & 255) << (8 * j);
        }
        hw[w] = hu; lw[w] = lu;
    }
    *reinterpret_cast<uint4*>(Ahi + (size_t)m * KK + tid * 16) = make_uint4(hw[0], hw[1], hw[2], hw[3]);
    *reinterpret_cast<uint4*>(Alo + (size_t)m * KK + tid * 16) = make_uint4(lw[0], lw[1], lw[2], lw[3]);
}

// ---------------------------------------------------------------------------
// Prep W: int4 nibbles -> exact s8 (w = q - 8), N-major [N][K].
// One thread = one n column x 64 k.
// ---------------------------------------------------------------------------
__global__ void prep_w_kernel(const int* __restrict__ Bp, int8_t* __restrict__ W) {
    int n   = blockIdx.x * 256 + threadIdx.x;
    int kp0 = blockIdx.y * 8;
    int8_t* dst = W + (size_t)n * KK + kp0 * 8;
#pragma unroll
    for (int r = 0; r < 8; r++) {
        int p = Bp[(size_t)(kp0 + r) * NN + n];
        uint32_t u0 = 0, u1 = 0;
#pragma unroll
        for (int j = 0; j < 4; j++) {
            int w0 = ((p >> (4 * j)) & 0xF) - 8;
            int w1 = ((p >> (4 * (j + 4))) & 0xF) - 8;
            u0 |= (uint32_t)(w0 & 255) << (8 * j);
            u1 |= (uint32_t)(w1 & 255) << (8 * j);
        }
        *reinterpret_cast<uint2*>(dst + r * 8) = make_uint2(u0, u1);
    }
}

// ---------------------------------------------------------------------------
// GEMM: CTA 128x128, 256 thr, 8 warps (4m x 2n), warp tile 32x64.
// Per K-group (128): 4 chunks of k32; IMMA hi-pass + lo-pass; per-group
// combine with s[g, col] from double-buffered smem staging; final x alpha.
// SMEM stage: [A_hi 16KB][A_lo 16KB][W 16KB]; row=128B, chunk swizzle c^(row&7).
// ---------------------------------------------------------------------------
#define STAGE_BYTES 49152
#define OFF_LO 16384
#define OFF_W  32768
#define SBUF_OFF (STAGES * STAGE_BYTES)      // 196608
#define SMEM_BYTES (SBUF_OFF + 1024)

__device__ __forceinline__ uint32_t smem_u32(const void* p) {
    uint32_t a;
    asm("{ .reg .u64 t; cvta.to.shared.u64 t, %1; cvt.u32.u64 %0, t; }" : "=r"(a) : "l"(p));
    return a;
}

#define CP_ASYNC16(smem, gmem) \
    asm volatile("cp.async.cg.shared.global [%0], [%1], 16;" :: "r"(smem), "l"(gmem))
#define CP_COMMIT() asm volatile("cp.async.commit_group;" ::: "memory")
#define CP_WAIT2()  asm volatile("cp.async.wait_group 2;" ::: "memory")

#define LDSM_X4(r, addr) \
    asm volatile("ldmatrix.sync.aligned.m8n8.x4.shared.b16 {%0,%1,%2,%3}, [%4];" \
        : "=r"((r)[0]), "=r"((r)[1]), "=r"((r)[2]), "=r"((r)[3]) : "r"(addr))

#define IMMA_ACC(d, a, b0, b1) \
    asm volatile("mma.sync.aligned.m16n8k32.row.col.s32.s8.s8.s32 " \
        "{%0,%1,%2,%3}, {%4,%5,%6,%7}, {%8,%9}, {%0,%1,%2,%3};" \
        : "+r"((d)[0]), "+r"((d)[1]), "+r"((d)[2]), "+r"((d)[3]) \
        : "r"((a)[0]), "r"((a)[1]), "r"((a)[2]), "r"((a)[3]), "r"(b0), "r"(b1))

#define IMMA_ZERO(d, a, b0, b1) \
    asm volatile("mma.sync.aligned.m16n8k32.row.col.s32.s8.s8.s32 " \
        "{%0,%1,%2,%3}, {%4,%5,%6,%7}, {%8,%9}, {%10,%10,%10,%10};" \
        : "=r"((d)[0]), "=r"((d)[1]), "=r"((d)[2]), "=r"((d)[3]) \
        : "r"((a)[0]), "r"((a)[1]), "r"((a)[2]), "r"((a)[3]), "r"(b0), "r"(b1), "r"(0))

__global__ __launch_bounds__(256, 1) void gemm_kernel(
    const int8_t* __restrict__ gAhi, const int8_t* __restrict__ gAlo,
    const int8_t* __restrict__ gW,   const float* __restrict__ gS,
    const float* __restrict__ gAl,   float* __restrict__ C)
{
    extern __shared__ char smem[];
    const uint32_t sbase = smem_u32(smem);
    const int tid = threadIdx.x, wid = tid >> 5, lid = tid & 31;

    // CTA swizzle: 8-wide m-bands sweeping n
    const int TILES_N = NN / TNT;     // 64
    int bid  = blockIdx.x;
    int band = bid / (8 * TILES_N);
    int rem  = bid % (8 * TILES_N);
    const int m0 = (band * 8 + (rem % 8)) * TMT;
    const int n0 = (rem / 8) * TNT;

    const int warpM = (wid & 3) * 32;   // 4 m-warps
    const int warpN = (wid >> 2) * 64;  // 2 n-warps

    // cp.async: 12 chunks/thread (A_hi 4, A_lo 4, W 4); persistent pointers
    const int vb = tid >> 3, cchk = tid & 7;
    const uint32_t soffBase = vb * 128 + ((cchk ^ (vb & 7)) << 4);
    const int8_t* pHi = gAhi + (size_t)(m0 + vb) * KK + cchk * 16;
    const int8_t* pLo = gAlo + (size_t)(m0 + vb) * KK + cchk * 16;
    const int8_t* pW  = gW  + (size_t)(n0 + vb) * KK + cchk * 16;

    // Prologue: fill STAGES-1 stages
#pragma unroll
    for (int p = 0; p < STAGES - 1; p++) {
        uint32_t sst = sbase + p * STAGE_BYTES + soffBase;
#pragma unroll
        for (int ck = 0; ck < 4; ck++) {
            CP_ASYNC16(sst + ck * 4096,          pHi + ck * 131072);
            CP_ASYNC16(sst + ck * 4096 + OFF_LO, pLo + ck * 131072);
            CP_ASYNC16(sst + ck * 4096 + OFF_W,  pW  + ck * 131072);
        }
        pHi += 128; pLo += 128; pW += 128;
        CP_COMMIT();
    }
    // Stage s for group 0 into buffer 0 (visible after first barrier)
    if (tid < 128)
        *reinterpret_cast<float*>(smem + SBUF_OFF + tid * 4) = gS[n0 + tid];

    float facc[2][8][4];
#pragma unroll
    for (int mi = 0; mi < 2; mi++)
#pragma unroll
        for (int ni = 0; ni < 8; ni++)
#pragma unroll
            for (int v = 0; v < 4; v++) facc[mi][ni][v] = 0.f;
    int accH[2][8][4], accL[2][8][4];

    const int lrow = lid & 15, lhalf = lid >> 4, lsw = lrow & 7;
    uint32_t aRow[2], bRow[4];
#pragma unroll
    for (int i = 0; i < 2; i++) aRow[i] = (warpM + i * 16 + lrow) * 128;
#pragma unroll
    for (int i = 0; i < 4; i++) bRow[i] = (warpN + i * 16 + lrow) * 128;
    const uint32_t scolBase = (uint32_t)(warpN + (lid & 3) * 2) * 4;

    for (int g = 0; g < K_ITERS; g++) {
        CP_WAIT2();
        __syncthreads();

        const int st = g % STAGES;
        const int ldst = (g + STAGES - 1) % STAGES;
        const bool doLoad = (g + STAGES - 1 < K_ITERS);
        const uint32_t aH = sbase + st * STAGE_BYTES;
        const uint32_t aL = aH + OFF_LO;
        const uint32_t wB = aH + OFF_W;
        const uint32_t lsst = sbase + ldst * STAGE_BYTES + soffBase;

        // Stage next group's s into the other buffer
        if (tid < 128 && g + 1 < K_ITERS)
            *reinterpret_cast<float*>(smem + SBUF_OFF + ((g + 1) & 1) * 512 + tid * 4)
                = gS[(size_t)(g + 1) * NN + n0 + tid];

#pragma unroll
        for (int ck = 0; ck < 4; ck++) {
            const uint32_t off = (uint32_t)(((ck * 2 + lhalf) ^ lsw) << 4);
            uint32_t fb[4][4];
#pragma unroll
            for (int np = 0; np < 4; np++) LDSM_X4(fb[np], wB + bRow[np] + off);
            uint32_t fa[2][4];
#pragma unroll
            for (int mi = 0; mi < 2; mi++) LDSM_X4(fa[mi], aH + aRow[mi] + off);
            if (doLoad) {
                CP_ASYNC16(lsst + ck * 4096,          pHi + ck * 131072);
                CP_ASYNC16(lsst + ck * 4096 + OFF_LO, pLo + ck * 131072);
                CP_ASYNC16(lsst + ck * 4096 + OFF_W,  pW  + ck * 131072);
            }
            if (ck == 3) { CP_COMMIT(); }
            if (ck == 0) {
#pragma unroll
                for (int mi = 0; mi < 2; mi++)
#pragma unroll
                    for (int ni = 0; ni < 8; ni++)
                        IMMA_ZERO(accH[mi][ni], fa[mi], fb[ni >> 1][ni & 1], fb[ni >> 1][2 + (ni & 1)]);
            } else {
#pragma unroll
                for (int mi = 0; mi < 2; mi++)
#pragma unroll
                    for (int ni = 0; ni < 8; ni++)
                        IMMA_ACC(accH[mi][ni], fa[mi], fb[ni >> 1][ni & 1], fb[ni >> 1][2 + (ni & 1)]);
            }
            // lo pass: reuse fa regs
#pragma unroll
            for (int mi = 0; mi < 2; mi++) LDSM_X4(fa[mi], aL + aRow[mi] + off);
            if (ck == 0) {
#pragma unroll
                for (int mi = 0; mi < 2; mi++)
#pragma unroll
                    for (int ni = 0; ni < 8; ni++)
                        IMMA_ZERO(accL[mi][ni], fa[mi], fb[ni >> 1][ni & 1], fb[ni >> 1][2 + (ni & 1)]);
            } else {
#pragma unroll
                for (int mi = 0; mi < 2; mi++)
#pragma unroll
                    for (int ni = 0; ni < 8; ni++)
                        IMMA_ACC(accL[mi][ni], fa[mi], fb[ni >> 1][ni & 1], fb[ni >> 1][2 + (ni & 1)]);
            }
        }
        pHi += 128; pLo += 128; pW += 128;

        // Combine: facc += s[g,col] * (128*hi + lo)   (exact int, exact I2F)
        const char* sb = smem + SBUF_OFF + (g & 1) * 512;
#pragma unroll
        for (int ni = 0; ni < 8; ni++) {
            float2 sv = *reinterpret_cast<const float2*>(sb + scolBase + ni * 32);
#pragma unroll
            for (int mi = 0; mi < 2; mi++)
#pragma unroll
                for (int v = 0; v < 4; v++) {
                    int comb = accH[mi][ni][v] * 128 + accL[mi][ni][v];
                    facc[mi][ni][v] += ((v & 1) ? sv.y : sv.x) * (float)comb;
                }
        }
    }

    // Epilogue: x alpha_row, float2 stores
#pragma unroll
    for (int mi = 0; mi < 2; mi++) {
        int r0 = m0 + warpM + mi * 16 + (lid >> 2);
        float a0 = gAl[r0], a1 = gAl[r0 + 8];
#pragma unroll
        for (int ni = 0; ni < 8; ni++) {
            int col = n0 + warpN + ni * 8 + (lid & 3) * 2;
            float2 v0 = make_float2(facc[mi][ni][0] * a0, facc[mi][ni][1] * a0);
            float2 v1 = make_float2(facc[mi][ni][2] * a1, facc[mi][ni][3] * a1);
            *reinterpret_cast<float2*>(C + (size_t)r0 * NN + col)       = v0;
            *reinterpret_cast<float2*>(C + (size_t)(r0 + 8) * NN + col) = v1;
        }
    }
}

// ---------------------------------------------------------------------------
// Host launch
// ---------------------------------------------------------------------------
extern "C" void kernel_launch(void* const* d_in, const int* in_sizes, int n_in,
                              void* d_out, int out_size) {
    const float* A  = (const float*)d_in[0];
    const int*   Bp = (const int*)d_in[1];
    const float* sc = (const float*)d_in[2];
    float* C = (float*)d_out;

    void *pHi = nullptr, *pLo = nullptr, *pW = nullptr, *pAl = nullptr;
    cudaGetSymbolAddress(&pHi, g_Ahi);
    cudaGetSymbolAddress(&pLo, g_Alo);
    cudaGetSymbolAddress(&pW,  g_W);
    cudaGetSymbolAddress(&pAl, g_alpha);

    prep_a_kernel<<<MM, 256>>>(A, (int8_t*)pHi, (int8_t*)pLo, (float*)pAl);
    prep_w_kernel<<<dim3(NN / 256, (KK / 8) / 8), 256>>>(Bp, (int8_t*)pW);

    cudaFuncSetAttribute(gemm_kernel, cudaFuncAttributeMaxDynamicSharedMemorySize,
                         SMEM_BYTES);
    gemm_kernel<<<(MM / TMT) * (NN / TNT), 256, SMEM_BYTES>>>(
        (const int8_t*)pHi, (const int8_t*)pLo, (const int8_t*)pW,
        sc, (const float*)pAl, C);
}

// round 10
// speedup vs baseline: 5.3943x; 5.3943x over previous
#include <cuda_runtime.h>
#include <cuda_fp16.h>
#include <cstdint>

// Problem constants
#define MM 8192
#define NN 8192
#define KK 4096
#define TM 128
#define TN 256
#define KS 128              // K elems per pipeline stage (256B rows)
#define STAGES 2
#define K_ITERS (KK / KS)   // 32

// Static scratch (allocation-free rule: __device__ globals): 64 MB + 64 MB
__device__ __half g_Ah[(size_t)MM * KK];
__device__ __half g_Wh[(size_t)NN * KK];

// ---------------------------------------------------------------------------
// Fused prep kernel.
// Blocks [0, A_BLOCKS): A (fp32 -> fp16), 8 elems/thread.
// Blocks [A_BLOCKS, +W_BLOCKS): W (int4 dequant -> fp16 N-major), 64 k/thread.
// ---------------------------------------------------------------------------
#define A_BLOCKS (MM * KK / 8 / 256)             // 16384
#define W_BLOCKS ((NN / 256) * ((KK / 8) / 8))   // 2048

__global__ void prep_kernel(const float* __restrict__ A, __half* __restrict__ Ah,
                            const int* __restrict__ Bp, const float* __restrict__ s,
                            __half* __restrict__ Wh) {
    int b = blockIdx.x;
    if (b < A_BLOCKS) {
        size_t base = ((size_t)b * 256 + threadIdx.x) * 8;
        float4 v0 = *reinterpret_cast<const float4*>(A + base);
        float4 v1 = *reinterpret_cast<const float4*>(A + base + 4);
        union { __half h[8]; uint4 u; } out;
        out.h[0] = __float2half(v0.x); out.h[1] = __float2half(v0.y);
        out.h[2] = __float2half(v0.z); out.h[3] = __float2half(v0.w);
        out.h[4] = __float2half(v1.x); out.h[5] = __float2half(v1.y);
        out.h[6] = __float2half(v1.z); out.h[7] = __float2half(v1.w);
        *reinterpret_cast<uint4*>(Ah + base) = out.u;
    } else {
        int bw  = b - A_BLOCKS;
        int n   = (bw & 31) * 256 + threadIdx.x;      // 32 x-blocks
        int kp0 = (bw >> 5) * 8;                      // 8 packed rows = 64 k
        float sv = s[(size_t)(kp0 >> 4) * NN + n];    // group = kp/16
        __half* dst = Wh + (size_t)n * KK + kp0 * 8;
#pragma unroll
        for (int r = 0; r < 8; r++) {
            int packed = Bp[(size_t)(kp0 + r) * NN + n];
            union { __half h[8]; uint4 u; } out;
#pragma unroll
            for (int j = 0; j < 8; j++) {
                int q = (packed >> (4 * j)) & 0xF;
                out.h[j] = __float2half((float)(q - 8) * sv);
            }
            *reinterpret_cast<uint4*>(dst + r * 8) = out.u;
        }
    }
}

// ---------------------------------------------------------------------------
// GEMM: C[M,N] = Ah @ Wh^T (fp16 in, f32 acc)
// CTA 128x256, 512 threads, 16 warps (2m x 8n), warp tile 64x32.
// 2-stage cp.async pipeline, KS=128 (256B rows, 16 chunks, swizzle c^(row&7)).
// Single base pointers + compile-time offsets (ptxas folds into [R+imm]).
// ---------------------------------------------------------------------------
#define A_STAGE_BYTES 32768              // 128 x 128 x 2
#define B_STAGE_BYTES 65536              // 256 x 128 x 2
#define B_REGION (STAGES * A_STAGE_BYTES)                       // 65536
#define SMEM_BYTES (STAGES * (A_STAGE_BYTES + B_STAGE_BYTES))   // 196608
#define ROWSTEP (32 * KK)                // halves: 32 rows of gmem
#define SROWSTEP 8192                    // bytes: 32 rows of smem stage

__device__ __forceinline__ uint32_t smem_u32(const void* p) {
    uint32_t a;
    asm("{ .reg .u64 t; cvta.to.shared.u64 t, %1; cvt.u32.u64 %0, t; }" : "=r"(a) : "l"(p));
    return a;
}

#define CP_ASYNC16(smem, gmem) \
    asm volatile("cp.async.cg.shared.global [%0], [%1], 16;" :: "r"(smem), "l"(gmem))
#define CP_COMMIT() asm volatile("cp.async.commit_group;" ::: "memory")
#define CP_WAIT0()  asm volatile("cp.async.wait_group 0;" ::: "memory")

#define LDSM_X4(r, addr) \
    asm volatile("ldmatrix.sync.aligned.m8n8.x4.shared.b16 {%0,%1,%2,%3}, [%4];" \
        : "=r"((r)[0]), "=r"((r)[1]), "=r"((r)[2]), "=r"((r)[3]) : "r"(addr))

#define MMA16816(d, a, b0, b1) \
    asm volatile("mma.sync.aligned.m16n8k16.row.col.f32.f16.f16.f32 " \
        "{%0,%1,%2,%3}, {%4,%5,%6,%7}, {%8,%9}, {%0,%1,%2,%3};" \
        : "+f"((d)[0]), "+f"((d)[1]), "+f"((d)[2]), "+f"((d)[3]) \
        : "r"((a)[0]), "r"((a)[1]), "r"((a)[2]), "r"((a)[3]), "r"(b0), "r"(b1))

__global__ __launch_bounds__(512, 1) void gemm_kernel(
    const __half* __restrict__ gA,
    const __half* __restrict__ gB,
    float* __restrict__ C)
{
    extern __shared__ char smem[];
    const uint32_t sbase = smem_u32(smem);
    const int tid = threadIdx.x, wid = tid >> 5, lid = tid & 31;

    // CTA swizzle: 8-wide m-bands sweeping n (L2 reuse)
    const int TILES_N = NN / TN;        // 32
    int bid  = blockIdx.x;
    int band = bid / (8 * TILES_N);
    int rem  = bid % (8 * TILES_N);
    const int m0 = (band * 8 + (rem % 8)) * TM;
    const int n0 = (rem / 8) * TN;

    const int warpM = (wid & 1) * 64;   // 2 m-warps
    const int warpN = (wid >> 1) * 32;  // 8 n-warps

    // cp.async mapping: base row = tid>>4 (0..31), chunk c = tid&15 (16B units).
    // Pass r adds 32 rows: gmem += r*ROWSTEP halves, smem += r*SROWSTEP bytes.
    // Swizzle key (row&7) is r-invariant (32 % 8 == 0).
    const int vb = tid >> 4, cchk = tid & 15;
    const uint32_t soffBase = (uint32_t)vb * 256 + (uint32_t)((cchk ^ (vb & 7)) << 4);
    const __half* pAg = gA + (size_t)(m0 + vb) * KK + cchk * 8;
    const __half* pBg = gB + (size_t)(n0 + vb) * KK + cchk * 8;

    // Prologue: fill stage 0
    {
        const uint32_t sa = sbase + soffBase;
        const uint32_t sb = sbase + B_REGION + soffBase;
#pragma unroll
        for (int r = 0; r < 4; r++) CP_ASYNC16(sa + r * SROWSTEP, pAg + (size_t)r * ROWSTEP);
#pragma unroll
        for (int r = 0; r < 8; r++) CP_ASYNC16(sb + r * SROWSTEP, pBg + (size_t)r * ROWSTEP);
        CP_COMMIT();
        pAg += KS; pBg += KS;
    }

    float acc[4][4][4];
#pragma unroll
    for (int mi = 0; mi < 4; mi++)
#pragma unroll
        for (int ni = 0; ni < 4; ni++)
#pragma unroll
            for (int v = 0; v < 4; v++) acc[mi][ni][v] = 0.f;

    const int lrow  = lid & 15;          // row within 16-row subtile
    const int lhalf = lid >> 4;          // k-chunk half (0/1)
    const int lsw   = lrow & 7;          // swizzle key

    const uint32_t aR0 = (uint32_t)(warpM + lrow) * 256;
    const uint32_t bR0 = (uint32_t)(warpN + lrow) * 256;

    for (int it = 0; it < K_ITERS; it++) {
        CP_WAIT0();
        __syncthreads();

        const int st = it & 1;
        const int ldst = st ^ 1;
        const bool doLoad = (it + 1 < K_ITERS);
        const uint32_t aBase = sbase + st * A_STAGE_BYTES;
        const uint32_t bBase = sbase + B_REGION + st * B_STAGE_BYTES;
        const uint32_t lsa = sbase + ldst * A_STAGE_BYTES + soffBase;
        const uint32_t lsb = sbase + B_REGION + ldst * B_STAGE_BYTES + soffBase;

#pragma unroll
        for (int kt = 0; kt < 8; kt++) {
            const uint32_t off = (uint32_t)(((kt * 2 + lhalf) ^ lsw) << 4);
            const uint32_t aAdr = aBase + aR0 + off;
            const uint32_t bAdr = bBase + bR0 + off;
            uint32_t fb[2][4];
            LDSM_X4(fb[0], bAdr);
            LDSM_X4(fb[1], bAdr + 4096);
            uint32_t fa[4][4];
#pragma unroll
            for (int mi = 0; mi < 4; mi++)
                LDSM_X4(fa[mi], aAdr + mi * 4096);
            // Next stage's cp.asyncs in kt0-3 (3 per slot), awaited >= 4 kt later
            if (doLoad && kt < 4) {
                CP_ASYNC16(lsa + kt * SROWSTEP, pAg + (size_t)kt * ROWSTEP);
                CP_ASYNC16(lsb + kt * SROWSTEP, pBg + (size_t)kt * ROWSTEP);
                CP_ASYNC16(lsb + (kt + 4) * SROWSTEP, pBg + (size_t)(kt + 4) * ROWSTEP);
            }
            if (kt == 3) { CP_COMMIT(); }
#pragma unroll
            for (int mi = 0; mi < 4; mi++)
#pragma unroll
                for (int ni = 0; ni < 4; ni++) {
                    const int np = ni >> 1, h = ni & 1;
                    MMA16816(acc[mi][ni], fa[mi], fb[np][h], fb[np][2 + h]);
                }
        }
        pAg += KS; pBg += KS;
    }

    // Epilogue: direct fp32 stores (coalesced float2 per thread)
#pragma unroll
    for (int mi = 0; mi < 4; mi++) {
        int row = m0 + warpM + mi * 16 + (lid >> 2);
#pragma unroll
        for (int ni = 0; ni < 4; ni++) {
            int col = n0 + warpN + ni * 8 + (lid & 3) * 2;
            float2 v0 = make_float2(acc[mi][ni][0], acc[mi][ni][1]);
            float2 v1 = make_float2(acc[mi][ni][2], acc[mi][ni][3]);
            *reinterpret_cast<float2*>(C + (size_t)row * NN + col)       = v0;
            *reinterpret_cast<float2*>(C + (size_t)(row + 8) * NN + col) = v1;
        }
    }
}

// ---------------------------------------------------------------------------
// Host launch
// ---------------------------------------------------------------------------
extern "C" void kernel_launch(void* const* d_in, const int* in_sizes, int n_in,
                              void* d_out, int out_size) {
    const float* A  = (const float*)d_in[0];
    const int*   Bp = (const int*)d_in[1];
    const float* sc = (const float*)d_in[2];
    float* C = (float*)d_out;

    void* pAh = nullptr; void* pWh = nullptr;
    cudaGetSymbolAddress(&pAh, g_Ah);
    cudaGetSymbolAddress(&pWh, g_Wh);

    prep_kernel<<<A_BLOCKS + W_BLOCKS, 256>>>(A, (__half*)pAh, Bp, sc, (__half*)pWh);

    cudaFuncSetAttribute(gemm_kernel, cudaFuncAttributeMaxDynamicSharedMemorySize,
                         SMEM_BYTES);
    gemm_kernel<<<(MM / TM) * (NN / TN), 512, SMEM_BYTES>>>(
        (const __half*)pAh, (const __half*)pWh, C);
}

// round 11
// speedup vs baseline: 5.4171x; 1.0042x over previous
#include <cuda_runtime.h>
#include <cuda_fp16.h>
#include <cstdint>

// Problem constants
#define MM 8192
#define NN 8192
#define KK 4096
#define TM 128
#define TN 256
#define KS 128              // K elems per pipeline stage (256B rows)
#define STAGES 2
#define K_ITERS (KK / KS)   // 32

// Static scratch (allocation-free rule: __device__ globals): 64 MB + 64 MB
__device__ __half g_Ah[(size_t)MM * KK];
__device__ __half g_Wh[(size_t)NN * KK];

// ---------------------------------------------------------------------------
// Fused prep kernel (512 threads).
// Blocks [0, A_BLOCKS): A (fp32 -> fp16), 8 elems/thread.
// Blocks [A_BLOCKS, +W_BLOCKS): W (int4 dequant -> fp16 N-major), 64 k/thread.
// ---------------------------------------------------------------------------
#define A_BLOCKS (MM * KK / 8 / 512)             // 8192
#define W_BLOCKS ((NN / 512) * ((KK / 8) / 8))   // 1024

__global__ void prep_kernel(const float* __restrict__ A, __half* __restrict__ Ah,
                            const int* __restrict__ Bp, const float* __restrict__ s,
                            __half* __restrict__ Wh) {
    int b = blockIdx.x;
    if (b < A_BLOCKS) {
        size_t base = ((size_t)b * 512 + threadIdx.x) * 8;
        float4 v0 = *reinterpret_cast<const float4*>(A + base);
        float4 v1 = *reinterpret_cast<const float4*>(A + base + 4);
        union { __half h[8]; uint4 u; } out;
        out.h[0] = __float2half(v0.x); out.h[1] = __float2half(v0.y);
        out.h[2] = __float2half(v0.z); out.h[3] = __float2half(v0.w);
        out.h[4] = __float2half(v1.x); out.h[5] = __float2half(v1.y);
        out.h[6] = __float2half(v1.z); out.h[7] = __float2half(v1.w);
        *reinterpret_cast<uint4*>(Ah + base) = out.u;
    } else {
        int bw  = b - A_BLOCKS;
        int n   = (bw & 15) * 512 + threadIdx.x;      // 16 x-blocks
        int kp0 = (bw >> 4) * 8;                      // 8 packed rows = 64 k
        float sv = s[(size_t)(kp0 >> 4) * NN + n];    // group = kp/16
        __half* dst = Wh + (size_t)n * KK + kp0 * 8;
#pragma unroll
        for (int r = 0; r < 8; r++) {
            int packed = Bp[(size_t)(kp0 + r) * NN + n];
            union { __half h[8]; uint4 u; } out;
#pragma unroll
            for (int j = 0; j < 8; j++) {
                int q = (packed >> (4 * j)) & 0xF;
                out.h[j] = __float2half((float)(q - 8) * sv);
            }
            *reinterpret_cast<uint4*>(dst + r * 8) = out.u;
        }
    }
}

// ---------------------------------------------------------------------------
// GEMM: C[M,N] = Ah @ Wh^T (fp16 in, f32 acc)
// CTA 128x256, 512 threads, 16 warps (2m x 8n), warp tile 64x32.
// 2-stage cp.async pipeline, KS=128 (256B rows, 16 chunks, swizzle c^(row&7)).
// All stage base addresses hoisted; per-it selection by parity.
// ---------------------------------------------------------------------------
#define A_STAGE_BYTES 32768              // 128 x 128 x 2
#define B_STAGE_BYTES 65536              // 256 x 128 x 2
#define B_REGION (STAGES * A_STAGE_BYTES)                       // 65536
#define SMEM_BYTES (STAGES * (A_STAGE_BYTES + B_STAGE_BYTES))   // 196608
#define ROWSTEP (32 * KK)                // halves: 32 rows of gmem
#define SROWSTEP 8192                    // bytes: 32 rows of smem stage

__device__ __forceinline__ uint32_t smem_u32(const void* p) {
    uint32_t a;
    asm("{ .reg .u64 t; cvta.to.shared.u64 t, %1; cvt.u32.u64 %0, t; }" : "=r"(a) : "l"(p));
    return a;
}

#define CP_ASYNC16(smem, gmem) \
    asm volatile("cp.async.cg.shared.global [%0], [%1], 16;" :: "r"(smem), "l"(gmem))
#define CP_COMMIT() asm volatile("cp.async.commit_group;" ::: "memory")
#define CP_WAIT0()  asm volatile("cp.async.wait_group 0;" ::: "memory")

#define LDSM_X4(r, addr) \
    asm volatile("ldmatrix.sync.aligned.m8n8.x4.shared.b16 {%0,%1,%2,%3}, [%4];" \
        : "=r"((r)[0]), "=r"((r)[1]), "=r"((r)[2]), "=r"((r)[3]) : "r"(addr))

#define MMA16816(d, a, b0, b1) \
    asm volatile("mma.sync.aligned.m16n8k16.row.col.f32.f16.f16.f32 " \
        "{%0,%1,%2,%3}, {%4,%5,%6,%7}, {%8,%9}, {%0,%1,%2,%3};" \
        : "+f"((d)[0]), "+f"((d)[1]), "+f"((d)[2]), "+f"((d)[3]) \
        : "r"((a)[0]), "r"((a)[1]), "r"((a)[2]), "r"((a)[3]), "r"(b0), "r"(b1))

__global__ __launch_bounds__(512, 1) void gemm_kernel(
    const __half* __restrict__ gA,
    const __half* __restrict__ gB,
    float* __restrict__ C)
{
    extern __shared__ char smem[];
    const uint32_t sbase = smem_u32(smem);
    const int tid = threadIdx.x, wid = tid >> 5, lid = tid & 31;

    // CTA swizzle: 8-wide m-bands sweeping n (L2 reuse)
    const int TILES_N = NN / TN;        // 32
    int bid  = blockIdx.x;
    int band = bid / (8 * TILES_N);
    int rem  = bid % (8 * TILES_N);
    const int m0 = (band * 8 + (rem % 8)) * TM;
    const int n0 = (rem / 8) * TN;

    const int warpM = (wid & 1) * 64;   // 2 m-warps
    const int warpN = (wid >> 1) * 32;  // 8 n-warps

    // cp.async mapping: base row = tid>>4 (0..31), chunk c = tid&15.
    const int vb = tid >> 4, cchk = tid & 15;
    const uint32_t soffBase = (uint32_t)vb * 256 + (uint32_t)((cchk ^ (vb & 7)) << 4);
    const __half* pAg = gA + (size_t)(m0 + vb) * KK + cchk * 8;
    const __half* pBg = gB + (size_t)(n0 + vb) * KK + cchk * 8;

    // Hoisted cp.async destination bases (per parity)
    const uint32_t wA0 = sbase + soffBase;
    const uint32_t wA1 = wA0 + A_STAGE_BYTES;
    const uint32_t wB0 = sbase + B_REGION + soffBase;
    const uint32_t wB1 = wB0 + B_STAGE_BYTES;

    // Prologue: fill stage 0
    {
#pragma unroll
        for (int r = 0; r < 4; r++) CP_ASYNC16(wA0 + r * SROWSTEP, pAg + (size_t)r * ROWSTEP);
#pragma unroll
        for (int r = 0; r < 8; r++) CP_ASYNC16(wB0 + r * SROWSTEP, pBg + (size_t)r * ROWSTEP);
        CP_COMMIT();
        pAg += KS; pBg += KS;
    }

    float acc[4][4][4];
#pragma unroll
    for (int mi = 0; mi < 4; mi++)
#pragma unroll
        for (int ni = 0; ni < 4; ni++)
#pragma unroll
            for (int v = 0; v < 4; v++) acc[mi][ni][v] = 0.f;

    const int lrow  = lid & 15;          // row within 16-row subtile
    const int lhalf = lid >> 4;          // k-chunk half (0/1)
    const int lsw   = lrow & 7;          // swizzle key

    // Hoisted LDSM read bases (per parity)
    const uint32_t rA0 = sbase + (uint32_t)(warpM + lrow) * 256;
    const uint32_t rA1 = rA0 + A_STAGE_BYTES;
    const uint32_t rB0 = sbase + B_REGION + (uint32_t)(warpN + lrow) * 256;
    const uint32_t rB1 = rB0 + B_STAGE_BYTES;

    for (int it = 0; it < K_ITERS; it++) {
        CP_WAIT0();
        __syncthreads();

        const int st = it & 1;
        const bool doLoad = (it + 1 < K_ITERS);
        const uint32_t aR = st ? rA1 : rA0;
        const uint32_t bR = st ? rB1 : rB0;
        const uint32_t lA = st ? wA0 : wA1;     // write opposite parity
        const uint32_t lB = st ? wB0 : wB1;

#pragma unroll
        for (int kt = 0; kt < 8; kt++) {
            const uint32_t off = (uint32_t)(((kt * 2 + lhalf) ^ lsw) << 4);
            const uint32_t aAdr = aR + off;
            const uint32_t bAdr = bR + off;
            uint32_t fb[2][4];
            LDSM_X4(fb[0], bAdr);
            LDSM_X4(fb[1], bAdr + 4096);
            uint32_t fa[4][4];
#pragma unroll
            for (int mi = 0; mi < 4; mi++)
                LDSM_X4(fa[mi], aAdr + mi * 4096);
            // Next stage's cp.asyncs in kt0-3 (3 per slot), awaited >= 4 kt later
            if (doLoad && kt < 4) {
                CP_ASYNC16(lA + kt * SROWSTEP, pAg + (size_t)kt * ROWSTEP);
                CP_ASYNC16(lB + kt * SROWSTEP, pBg + (size_t)kt * ROWSTEP);
                CP_ASYNC16(lB + (kt + 4) * SROWSTEP, pBg + (size_t)(kt + 4) * ROWSTEP);
            }
            if (kt == 3) { CP_COMMIT(); }
#pragma unroll
            for (int mi = 0; mi < 4; mi++)
#pragma unroll
                for (int ni = 0; ni < 4; ni++) {
                    const int np = ni >> 1, h = ni & 1;
                    MMA16816(acc[mi][ni], fa[mi], fb[np][h], fb[np][2 + h]);
                }
        }
        pAg += KS; pBg += KS;
    }

    // Epilogue: direct fp32 stores (coalesced float2 per thread)
#pragma unroll
    for (int mi = 0; mi < 4; mi++) {
        int row = m0 + warpM + mi * 16 + (lid >> 2);
#pragma unroll
        for (int ni = 0; ni < 4; ni++) {
            int col = n0 + warpN + ni * 8 + (lid & 3) * 2;
            float2 v0 = make_float2(acc[mi][ni][0], acc[mi][ni][1]);
            float2 v1 = make_float2(acc[mi][ni][2], acc[mi][ni][3]);
            *reinterpret_cast<float2*>(C + (size_t)row * NN + col)       = v0;
            *reinterpret_cast<float2*>(C + (size_t)(row + 8) * NN + col) = v1;
        }
    }
}

// ---------------------------------------------------------------------------
// Host launch
// ---------------------------------------------------------------------------
extern "C" void kernel_launch(void* const* d_in, const int* in_sizes, int n_in,
                              void* d_out, int out_size) {
    const float* A  = (const float*)d_in[0];
    const int*   Bp = (const int*)d_in[1];
    const float* sc = (const float*)d_in[2];
    float* C = (float*)d_out;

    void* pAh = nullptr; void* pWh = nullptr;
    cudaGetSymbolAddress(&pAh, g_Ah);
    cudaGetSymbolAddress(&pWh, g_Wh);

    prep_kernel<<<A_BLOCKS + W_BLOCKS, 512>>>(A, (__half*)pAh, Bp, sc, (__half*)pWh);

    cudaFuncSetAttribute(gemm_kernel, cudaFuncAttributeMaxDynamicSharedMemorySize,
                         SMEM_BYTES);
    gemm_kernel<<<(MM / TM) * (NN / TN), 512, SMEM_BYTES>>>(
        (const __half*)pAh, (const __half*)pWh, C);
}

// round 12
// speedup vs baseline: 5.4558x; 1.0071x over previous
#include <cuda_runtime.h>
#include <cuda_fp16.h>
#include <cstdint>

// Problem constants
#define MM 8192
#define NN 8192
#define KK 4096
#define TM 128
#define TN 256
#define KS 128              // K elems per pipeline stage (256B rows)
#define STAGES 2
#define K_ITERS (KK / KS)   // 32 (even)

// Static scratch (allocation-free rule: __device__ globals): 64 MB + 64 MB
__device__ __half g_Ah[(size_t)MM * KK];
__device__ __half g_Wh[(size_t)NN * KK];

// ---------------------------------------------------------------------------
// Fused prep kernel (512 threads).
// ---------------------------------------------------------------------------
#define A_BLOCKS (MM * KK / 8 / 512)             // 8192
#define W_BLOCKS ((NN / 512) * ((KK / 8) / 8))   // 1024

__global__ void prep_kernel(const float* __restrict__ A, __half* __restrict__ Ah,
                            const int* __restrict__ Bp, const float* __restrict__ s,
                            __half* __restrict__ Wh) {
    int b = blockIdx.x;
    if (b < A_BLOCKS) {
        size_t base = ((size_t)b * 512 + threadIdx.x) * 8;
        float4 v0 = *reinterpret_cast<const float4*>(A + base);
        float4 v1 = *reinterpret_cast<const float4*>(A + base + 4);
        union { __half h[8]; uint4 u; } out;
        out.h[0] = __float2half(v0.x); out.h[1] = __float2half(v0.y);
        out.h[2] = __float2half(v0.z); out.h[3] = __float2half(v0.w);
        out.h[4] = __float2half(v1.x); out.h[5] = __float2half(v1.y);
        out.h[6] = __float2half(v1.z); out.h[7] = __float2half(v1.w);
        *reinterpret_cast<uint4*>(Ah + base) = out.u;
    } else {
        int bw  = b - A_BLOCKS;
        int n   = (bw & 15) * 512 + threadIdx.x;      // 16 x-blocks
        int kp0 = (bw >> 4) * 8;                      // 8 packed rows = 64 k
        float sv = s[(size_t)(kp0 >> 4) * NN + n];    // group = kp/16
        __half* dst = Wh + (size_t)n * KK + kp0 * 8;
#pragma unroll
        for (int r = 0; r < 8; r++) {
            int packed = Bp[(size_t)(kp0 + r) * NN + n];
            union { __half h[8]; uint4 u; } out;
#pragma unroll
            for (int j = 0; j < 8; j++) {
                int q = (packed >> (4 * j)) & 0xF;
                out.h[j] = __float2half((float)(q - 8) * sv);
            }
            *reinterpret_cast<uint4*>(dst + r * 8) = out.u;
        }
    }
}

// ---------------------------------------------------------------------------
// GEMM: C[M,N] = Ah @ Wh^T (fp16 in, f32 acc)
// CTA 128x256, 512 threads, 16 warps (2m x 8n), warp tile 64x32.
// 2-stage cp.async pipeline, KS=128; outer loop unrolled x2 (hard parity).
// ---------------------------------------------------------------------------
#define A_STAGE_BYTES 32768              // 128 x 128 x 2
#define B_STAGE_BYTES 65536              // 256 x 128 x 2
#define B_REGION (STAGES * A_STAGE_BYTES)                       // 65536
#define SMEM_BYTES (STAGES * (A_STAGE_BYTES + B_STAGE_BYTES))   // 196608
#define ROWSTEP (32 * KK)                // halves: 32 rows of gmem
#define SROWSTEP 8192                    // bytes: 32 rows of smem stage

__device__ __forceinline__ uint32_t smem_u32(const void* p) {
    uint32_t a;
    asm("{ .reg .u64 t; cvta.to.shared.u64 t, %1; cvt.u32.u64 %0, t; }" : "=r"(a) : "l"(p));
    return a;
}

#define CP_ASYNC16(smem, gmem) \
    asm volatile("cp.async.cg.shared.global [%0], [%1], 16;" :: "r"(smem), "l"(gmem))
#define CP_COMMIT() asm volatile("cp.async.commit_group;" ::: "memory")
#define CP_WAIT0()  asm volatile("cp.async.wait_group 0;" ::: "memory")

#define LDSM_X4(r, addr) \
    asm volatile("ldmatrix.sync.aligned.m8n8.x4.shared.b16 {%0,%1,%2,%3}, [%4];" \
        : "=r"((r)[0]), "=r"((r)[1]), "=r"((r)[2]), "=r"((r)[3]) : "r"(addr))

#define MMA16816(d, a, b0, b1) \
    asm volatile("mma.sync.aligned.m16n8k16.row.col.f32.f16.f16.f32 " \
        "{%0,%1,%2,%3}, {%4,%5,%6,%7}, {%8,%9}, {%0,%1,%2,%3};" \
        : "+f"((d)[0]), "+f"((d)[1]), "+f"((d)[2]), "+f"((d)[3]) \
        : "r"((a)[0]), "r"((a)[1]), "r"((a)[2]), "r"((a)[3]), "r"(b0), "r"(b1))

__global__ __launch_bounds__(512, 1) void gemm_kernel(
    const __half* __restrict__ gA,
    const __half* __restrict__ gB,
    float* __restrict__ C)
{
    extern __shared__ char smem[];
    const uint32_t sbase = smem_u32(smem);
    const int tid = threadIdx.x, wid = tid >> 5, lid = tid & 31;

    // CTA swizzle: 8-wide m-bands sweeping n (L2 reuse)
    const int TILES_N = NN / TN;        // 32
    int bid  = blockIdx.x;
    int band = bid / (8 * TILES_N);
    int rem  = bid % (8 * TILES_N);
    const int m0 = (band * 8 + (rem % 8)) * TM;
    const int n0 = (rem / 8) * TN;

    const int warpM = (wid & 1) * 64;   // 2 m-warps
    const int warpN = (wid >> 1) * 32;  // 8 n-warps

    // cp.async mapping: base row = tid>>4 (0..31), chunk c = tid&15.
    const int vb = tid >> 4, cchk = tid & 15;
    const uint32_t soffBase = (uint32_t)vb * 256 + (uint32_t)((cchk ^ (vb & 7)) << 4);
    const __half* pAg = gA + (size_t)(m0 + vb) * KK + cchk * 8;
    const __half* pBg = gB + (size_t)(n0 + vb) * KK + cchk * 8;

    // Hoisted cp.async destination bases (per parity)
    const uint32_t wA0 = sbase + soffBase;
    const uint32_t wA1 = wA0 + A_STAGE_BYTES;
    const uint32_t wB0 = sbase + B_REGION + soffBase;
    const uint32_t wB1 = wB0 + B_STAGE_BYTES;

    // Prologue: fill stage 0
    {
#pragma unroll
        for (int r = 0; r < 4; r++) CP_ASYNC16(wA0 + r * SROWSTEP, pAg + (size_t)r * ROWSTEP);
#pragma unroll
        for (int r = 0; r < 8; r++) CP_ASYNC16(wB0 + r * SROWSTEP, pBg + (size_t)r * ROWSTEP);
        CP_COMMIT();
        pAg += KS; pBg += KS;
    }

    float acc[4][4][4];
#pragma unroll
    for (int mi = 0; mi < 4; mi++)
#pragma unroll
        for (int ni = 0; ni < 4; ni++)
#pragma unroll
            for (int v = 0; v < 4; v++) acc[mi][ni][v] = 0.f;

    const int lrow  = lid & 15;          // row within 16-row subtile
    const int lhalf = lid >> 4;          // k-chunk half (0/1)
    const int lsw   = lrow & 7;          // swizzle key

    // Hoisted LDSM read bases (per parity)
    const uint32_t rA0 = sbase + (uint32_t)(warpM + lrow) * 256;
    const uint32_t rA1 = rA0 + A_STAGE_BYTES;
    const uint32_t rB0 = sbase + B_REGION + (uint32_t)(warpN + lrow) * 256;
    const uint32_t rB1 = rB0 + B_STAGE_BYTES;

    // One stage body: read (aR,bR), load next stage into (lA,lB).
    auto body = [&](uint32_t aR, uint32_t bR, uint32_t lA, uint32_t lB, bool doLoad) {
        CP_WAIT0();
        __syncthreads();
#pragma unroll
        for (int kt = 0; kt < 8; kt++) {
            const uint32_t off = (uint32_t)(((kt * 2 + lhalf) ^ lsw) << 4);
            const uint32_t aAdr = aR + off;
            const uint32_t bAdr = bR + off;
            uint32_t fa[4][4], fb[2][4];
            LDSM_X4(fa[0], aAdr);
            LDSM_X4(fb[0], bAdr);
            LDSM_X4(fb[1], bAdr + 4096);
            LDSM_X4(fa[1], aAdr + 4096);
            LDSM_X4(fa[2], aAdr + 8192);
            LDSM_X4(fa[3], aAdr + 12288);
            // Next stage's cp.asyncs: 2 per slot, kt0..5
            if (doLoad && kt < 6) {
                if (kt < 4) {
                    CP_ASYNC16(lA + kt * SROWSTEP, pAg + (size_t)kt * ROWSTEP);
                    CP_ASYNC16(lB + kt * SROWSTEP, pBg + (size_t)kt * ROWSTEP);
                } else {
                    CP_ASYNC16(lB + (2 * kt - 4) * SROWSTEP, pBg + (size_t)(2 * kt - 4) * ROWSTEP);
                    CP_ASYNC16(lB + (2 * kt - 3) * SROWSTEP, pBg + (size_t)(2 * kt - 3) * ROWSTEP);
                }
            }
            if (kt == 5) { CP_COMMIT(); }
#pragma unroll
            for (int mi = 0; mi < 4; mi++)
#pragma unroll
                for (int ni = 0; ni < 4; ni++) {
                    const int np = ni >> 1, h = ni & 1;
                    MMA16816(acc[mi][ni], fa[mi], fb[np][h], fb[np][2 + h]);
                }
        }
        pAg += KS; pBg += KS;
    };

#pragma unroll 1
    for (int it2 = 0; it2 < K_ITERS; it2 += 2) {
        body(rA0, rB0, wA1, wB1, true);                    // read st0, load st1
        body(rA1, rB1, wA0, wB0, it2 + 2 < K_ITERS);       // read st1, load st0
    }

    // Epilogue: direct fp32 stores (coalesced float2 per thread)
#pragma unroll
    for (int mi = 0; mi < 4; mi++) {
        int row = m0 + warpM + mi * 16 + (lid >> 2);
#pragma unroll
        for (int ni = 0; ni < 4; ni++) {
            int col = n0 + warpN + ni * 8 + (lid & 3) * 2;
            float2 v0 = make_float2(acc[mi][ni][0], acc[mi][ni][1]);
            float2 v1 = make_float2(acc[mi][ni][2], acc[mi][ni][3]);
            *reinterpret_cast<float2*>(C + (size_t)row * NN + col)       = v0;
            *reinterpret_cast<float2*>(C + (size_t)(row + 8) * NN + col) = v1;
        }
    }
}

// ---------------------------------------------------------------------------
// Host launch
// ---------------------------------------------------------------------------
extern "C" void kernel_launch(void* const* d_in, const int* in_sizes, int n_in,
                              void* d_out, int out_size) {
    const float* A  = (const float*)d_in[0];
    const int*   Bp = (const int*)d_in[1];
    const float* sc = (const float*)d_in[2];
    float* C = (float*)d_out;

    void* pAh = nullptr; void* pWh = nullptr;
    cudaGetSymbolAddress(&pAh, g_Ah);
    cudaGetSymbolAddress(&pWh, g_Wh);

    prep_kernel<<<A_BLOCKS + W_BLOCKS, 512>>>(A, (__half*)pAh, Bp, sc, (__half*)pWh);

    cudaFuncSetAttribute(gemm_kernel, cudaFuncAttributeMaxDynamicSharedMemorySize,
                         SMEM_BYTES);
    gemm_kernel<<<(MM / TM) * (NN / TN), 512, SMEM_BYTES>>>(
        (const __half*)pAh, (const __half*)pWh, C);
}